// round 3
// baseline (speedup 1.0000x reference)
#include <cuda_runtime.h>

#define TT 32
#define PP 16
#define NN 65536
#define HH 128
#define NTHREADS 128
#define NBLOCKS 512   // 512 blocks * 128 threads * 1 point = 65536

#define OFF_ARG (TT * NN * 3)      // 6291456
#define OFF_TL  (OFF_ARG + NN)     // 6356992

__device__ __forceinline__ unsigned long long packrep(float a) {
    unsigned long long r;
    asm("mov.b64 %0, {%1, %1};" : "=l"(r) : "f"(a));
    return r;
}
__device__ __forceinline__ void fma2(unsigned long long& d, unsigned long long a, unsigned long long b) {
    asm("fma.rn.f32x2 %0, %1, %2, %0;" : "+l"(d) : "l"(a), "l"(b));
}
__device__ __forceinline__ void unpack2(unsigned long long v, float& lo, float& hi) {
    asm("mov.b64 {%0, %1}, %2;" : "=f"(lo), "=f"(hi) : "l"(v));
}

__global__ void __launch_bounds__(NTHREADS) fused_kernel(
    const float* __restrict__ cano, const float* __restrict__ w1,
    const float* __restrict__ b1, const float* __restrict__ w2,
    const float* __restrict__ b2, const float* __restrict__ p6d,
    const float* __restrict__ pt, const float* __restrict__ gum,
    float* __restrict__ out)
{
    __shared__ float4 s_w1[HH];                        // w1 row + b1
    __shared__ __align__(16) float2 s_w2p[HH][8];      // w2 packed over p-pairs
    __shared__ float2 s_b2p[8];
    __shared__ __align__(16) float s_R[TT * PP][12];   // R rows + t

    const int tid = threadIdx.x;

    // ---- stage weights into shared memory ----
    s_w1[tid] = make_float4(w1[3 * tid], w1[3 * tid + 1], w1[3 * tid + 2], b1[tid]);

    #pragma unroll
    for (int k = 0; k < 8; k++) {
        int idx = k * NTHREADS + tid;     // 0..1023
        int h = idx & (HH - 1);
        int pp = idx >> 7;                // 0..7
        s_w2p[h][pp] = make_float2(w2[(2 * pp) * HH + h], w2[(2 * pp + 1) * HH + h]);
    }
    if (tid < 8) s_b2p[tid] = make_float2(b2[2 * tid], b2[2 * tid + 1]);

    // ---- per-block rotation table (tiny, redundant across blocks by design) ----
    #pragma unroll
    for (int k = 0; k < 4; k++) {
        int e = k * NTHREADS + tid;       // 0..511 = t*16+p
        float a1x = p6d[e * 6 + 0], a1y = p6d[e * 6 + 1], a1z = p6d[e * 6 + 2];
        float a2x = p6d[e * 6 + 3], a2y = p6d[e * 6 + 4], a2z = p6d[e * 6 + 5];
        float inv = rsqrtf(a1x * a1x + a1y * a1y + a1z * a1z);
        float b1x = a1x * inv, b1y = a1y * inv, b1z = a1z * inv;
        float d = b1x * a2x + b1y * a2y + b1z * a2z;
        float cx = a2x - d * b1x, cy = a2y - d * b1y, cz = a2z - d * b1z;
        float inv2 = rsqrtf(cx * cx + cy * cy + cz * cz);
        float b2x = cx * inv2, b2y = cy * inv2, b2z = cz * inv2;
        float b3x = b1y * b2z - b1z * b2y;
        float b3y = b1z * b2x - b1x * b2z;
        float b3z = b1x * b2y - b1y * b2x;
        float t0 = pt[e * 3 + 0], t1 = pt[e * 3 + 1], t2 = pt[e * 3 + 2];
        float* r = s_R[e];
        r[0] = b1x; r[1] = b1y; r[2] = b1z;
        r[3] = b2x; r[4] = b2y; r[5] = b2z;
        r[6] = b3x; r[7] = b3y; r[8] = b3z;
        r[9] = t0;  r[10] = t1; r[11] = t2;
        if (blockIdx.x == 0) {
            float* o = out + OFF_TL + e * 16;
            o[0] = b1x; o[1] = b1y; o[2]  = b1z; o[3]  = t0;
            o[4] = b2x; o[5] = b2y; o[6]  = b2z; o[7]  = t1;
            o[8] = b3x; o[9] = b3y; o[10] = b3z; o[11] = t2;
            o[12] = 0.f; o[13] = 0.f; o[14] = 0.f; o[15] = 1.f;
        }
    }
    __syncthreads();

    // ---- one point per thread ----
    const int n = blockIdx.x * NTHREADS + tid;
    const float xx = cano[n * 3], xy = cano[n * 3 + 1], xz = cano[n * 3 + 2];

    // prefetch gumbel (DRAM latency overlapped with the MLP loop)
    const float4* g4 = reinterpret_cast<const float4*>(gum + (size_t)n * PP);
    float4 g0 = g4[0], g1 = g4[1], g2 = g4[2], g3 = g4[3];

    unsigned long long seg[8];
    #pragma unroll
    for (int k = 0; k < 8; k++)
        seg[k] = *reinterpret_cast<const unsigned long long*>(&s_b2p[k]);

    // MLP: h = relu(x@w1^T + b1); seg = h@w2^T + b2, packed f32x2 over p-pairs
    #pragma unroll 8
    for (int h = 0; h < HH; h++) {
        float4 w = s_w1[h];
        float hv = fmaxf(fmaf(xx, w.x, fmaf(xy, w.y, fmaf(xz, w.z, w.w))), 0.0f);
        unsigned long long h2 = packrep(hv);
        const ulonglong2* wp = reinterpret_cast<const ulonglong2*>(&s_w2p[h][0]);
        ulonglong2 q0 = wp[0], q1 = wp[1], q2 = wp[2], q3 = wp[3];
        fma2(seg[0], h2, q0.x);
        fma2(seg[1], h2, q0.y);
        fma2(seg[2], h2, q1.x);
        fma2(seg[3], h2, q1.y);
        fma2(seg[4], h2, q2.x);
        fma2(seg[5], h2, q2.y);
        fma2(seg[6], h2, q3.x);
        fma2(seg[7], h2, q3.y);
    }

    float s[16];
    #pragma unroll
    for (int k = 0; k < 8; k++)
        unpack2(seg[k], s[2 * k], s[2 * k + 1]);

    // argmax(seg) (output 2), first-occurrence semantics
    int ia = 0;
    float m = s[0];
    #pragma unroll
    for (int p = 1; p < PP; p++)
        if (s[p] > m) { m = s[p]; ia = p; }
    out[OFF_ARG + n] = (float)ia;

    // selection = argmax(seg + gumbel)  (== argmax of gumbel-softmax, TAU>0)
    int sel = 0;
    float vm = -1e30f;
    {
        float a;
        a = s[0]  + g0.x; if (a > vm) { vm = a; sel = 0;  }
        a = s[1]  + g0.y; if (a > vm) { vm = a; sel = 1;  }
        a = s[2]  + g0.z; if (a > vm) { vm = a; sel = 2;  }
        a = s[3]  + g0.w; if (a > vm) { vm = a; sel = 3;  }
        a = s[4]  + g1.x; if (a > vm) { vm = a; sel = 4;  }
        a = s[5]  + g1.y; if (a > vm) { vm = a; sel = 5;  }
        a = s[6]  + g1.z; if (a > vm) { vm = a; sel = 6;  }
        a = s[7]  + g1.w; if (a > vm) { vm = a; sel = 7;  }
        a = s[8]  + g2.x; if (a > vm) { vm = a; sel = 8;  }
        a = s[9]  + g2.y; if (a > vm) { vm = a; sel = 9;  }
        a = s[10] + g2.z; if (a > vm) { vm = a; sel = 10; }
        a = s[11] + g2.w; if (a > vm) { vm = a; sel = 11; }
        a = s[12] + g3.x; if (a > vm) { vm = a; sel = 12; }
        a = s[13] + g3.y; if (a > vm) { vm = a; sel = 13; }
        a = s[14] + g3.z; if (a > vm) { vm = a; sel = 14; }
        a = s[15] + g3.w; if (a > vm) { vm = a; sel = 15; }
    }

    // pc_out[t,n,:] = R[t,sel] @ x + t[t,sel]
    #pragma unroll 4
    for (int t = 0; t < TT; t++) {
        const float4* R = reinterpret_cast<const float4*>(s_R[t * PP + sel]);
        float4 r0 = R[0], r1 = R[1], r2 = R[2];
        float o0 = fmaf(xx, r0.x, fmaf(xy, r0.y, fmaf(xz, r0.z, r2.y)));
        float o1 = fmaf(xx, r0.w, fmaf(xy, r1.x, fmaf(xz, r1.y, r2.z)));
        float o2 = fmaf(xx, r1.z, fmaf(xy, r1.w, fmaf(xz, r2.x, r2.w)));
        float* dst = out + (size_t)(t * NN + n) * 3;
        dst[0] = o0;
        dst[1] = o1;
        dst[2] = o2;
    }
}

extern "C" void kernel_launch(void* const* d_in, const int* in_sizes, int n_in,
                              void* d_out, int out_size) {
    (void)in_sizes; (void)n_in; (void)out_size;
    fused_kernel<<<NBLOCKS, NTHREADS>>>(
        (const float*)d_in[0],  // cano_pc
        (const float*)d_in[1],  // w1
        (const float*)d_in[2],  // b1
        (const float*)d_in[3],  // w2
        (const float*)d_in[4],  // b2
        (const float*)d_in[5],  // proposal_6d
        (const float*)d_in[6],  // proposal_t
        (const float*)d_in[7],  // gumbel
        (float*)d_out);
}

// round 4
// speedup vs baseline: 1.1515x; 1.1515x over previous
#include <cuda_runtime.h>

#define TT 32
#define PP 16
#define NN 65536
#define HH 128
#define NTHREADS 64
#define NBLOCKS 256   // 256 * 64 threads * 4 points = 65536
#define PTS 4

#define OFF_ARG (TT * NN * 3)      // 6291456
#define OFF_TL  (OFF_ARG + NN)     // 6356992

__device__ __forceinline__ unsigned long long packrep(float a) {
    unsigned long long r;
    asm("mov.b64 %0, {%1, %1};" : "=l"(r) : "f"(a));
    return r;
}
__device__ __forceinline__ void fma2(unsigned long long& d, unsigned long long a, unsigned long long b) {
    asm("fma.rn.f32x2 %0, %1, %2, %0;" : "+l"(d) : "l"(a), "l"(b));
}
__device__ __forceinline__ void unpack2(unsigned long long v, float& lo, float& hi) {
    asm("mov.b64 {%0, %1}, %2;" : "=f"(lo), "=f"(hi) : "l"(v));
}

__global__ void __launch_bounds__(NTHREADS) fused_kernel(
    const float* __restrict__ cano, const float* __restrict__ w1,
    const float* __restrict__ b1, const float* __restrict__ w2,
    const float* __restrict__ b2, const float* __restrict__ p6d,
    const float* __restrict__ pt, const float* __restrict__ gum,
    float* __restrict__ out)
{
    __shared__ float4 s_w1[HH];                        // w1 row + b1
    __shared__ __align__(16) float2 s_w2p[HH][8];      // w2 packed over p-pairs
    __shared__ float2 s_b2p[8];
    __shared__ __align__(16) float s_R[TT * PP][12];   // R rows + t

    const int tid = threadIdx.x;

    // ---- stage weights into shared memory ----
    #pragma unroll
    for (int k = 0; k < 2; k++) {
        int h = k * NTHREADS + tid;
        s_w1[h] = make_float4(w1[3 * h], w1[3 * h + 1], w1[3 * h + 2], b1[h]);
    }
    #pragma unroll
    for (int k = 0; k < 16; k++) {
        int idx = k * NTHREADS + tid;     // 0..1023
        int h = idx & (HH - 1);
        int pp = idx >> 7;                // 0..7
        s_w2p[h][pp] = make_float2(w2[(2 * pp) * HH + h], w2[(2 * pp + 1) * HH + h]);
    }
    if (tid < 8) s_b2p[tid] = make_float2(b2[2 * tid], b2[2 * tid + 1]);

    // ---- per-block rotation table (tiny, redundant across blocks by design) ----
    #pragma unroll
    for (int k = 0; k < 8; k++) {
        int e = k * NTHREADS + tid;       // 0..511 = t*16+p
        float a1x = p6d[e * 6 + 0], a1y = p6d[e * 6 + 1], a1z = p6d[e * 6 + 2];
        float a2x = p6d[e * 6 + 3], a2y = p6d[e * 6 + 4], a2z = p6d[e * 6 + 5];
        float inv = rsqrtf(a1x * a1x + a1y * a1y + a1z * a1z);
        float b1x = a1x * inv, b1y = a1y * inv, b1z = a1z * inv;
        float d = b1x * a2x + b1y * a2y + b1z * a2z;
        float cx = a2x - d * b1x, cy = a2y - d * b1y, cz = a2z - d * b1z;
        float inv2 = rsqrtf(cx * cx + cy * cy + cz * cz);
        float b2x = cx * inv2, b2y = cy * inv2, b2z = cz * inv2;
        float b3x = b1y * b2z - b1z * b2y;
        float b3y = b1z * b2x - b1x * b2z;
        float b3z = b1x * b2y - b1y * b2x;
        float t0 = pt[e * 3 + 0], t1 = pt[e * 3 + 1], t2 = pt[e * 3 + 2];
        float* r = s_R[e];
        r[0] = b1x; r[1] = b1y; r[2] = b1z;
        r[3] = b2x; r[4] = b2y; r[5] = b2z;
        r[6] = b3x; r[7] = b3y; r[8] = b3z;
        r[9] = t0;  r[10] = t1; r[11] = t2;
        if (blockIdx.x == 0) {
            float* o = out + OFF_TL + e * 16;
            o[0] = b1x; o[1] = b1y; o[2]  = b1z; o[3]  = t0;
            o[4] = b2x; o[5] = b2y; o[6]  = b2z; o[7]  = t1;
            o[8] = b3x; o[9] = b3y; o[10] = b3z; o[11] = t2;
            o[12] = 0.f; o[13] = 0.f; o[14] = 0.f; o[15] = 1.f;
        }
    }
    __syncthreads();

    // ---- four points per thread ----
    const int gtid = blockIdx.x * NTHREADS + tid;
    const int n0 = gtid * PTS;

    // coalesced point loads: 12 contiguous floats = 3x float4
    const float4* c4 = reinterpret_cast<const float4*>(cano + (size_t)n0 * 3);
    float4 ca = c4[0], cb = c4[1], cc = c4[2];
    float px[PTS], py[PTS], pz[PTS];
    px[0] = ca.x; py[0] = ca.y; pz[0] = ca.z;
    px[1] = ca.w; py[1] = cb.x; pz[1] = cb.y;
    px[2] = cb.z; py[2] = cb.w; pz[2] = cc.x;
    px[3] = cc.y; py[3] = cc.z; pz[3] = cc.w;

    // prefetch gumbel for all 4 points (DRAM latency hidden under MLP loop)
    const float4* g4 = reinterpret_cast<const float4*>(gum + (size_t)n0 * PP);
    float4 g[PTS][4];
    #pragma unroll
    for (int k = 0; k < PTS; k++) {
        g[k][0] = g4[4 * k + 0]; g[k][1] = g4[4 * k + 1];
        g[k][2] = g4[4 * k + 2]; g[k][3] = g4[4 * k + 3];
    }

    unsigned long long seg[PTS][8];
    #pragma unroll
    for (int k = 0; k < 8; k++) {
        unsigned long long bb = *reinterpret_cast<const unsigned long long*>(&s_b2p[k]);
        seg[0][k] = bb; seg[1][k] = bb; seg[2][k] = bb; seg[3][k] = bb;
    }

    // MLP: h = relu(x@w1^T + b1); seg = h@w2^T + b2 (f32x2 over p-pairs, 4 pts share LDS)
    #pragma unroll 4
    for (int h = 0; h < HH; h++) {
        float4 w = s_w1[h];
        const ulonglong2* wp = reinterpret_cast<const ulonglong2*>(&s_w2p[h][0]);
        ulonglong2 q0 = wp[0], q1 = wp[1];
        #pragma unroll
        for (int k = 0; k < PTS; k++) {
            float hv = fmaxf(fmaf(px[k], w.x, fmaf(py[k], w.y, fmaf(pz[k], w.z, w.w))), 0.0f);
            unsigned long long h2 = packrep(hv);
            fma2(seg[k][0], h2, q0.x);
            fma2(seg[k][1], h2, q0.y);
            fma2(seg[k][2], h2, q1.x);
            fma2(seg[k][3], h2, q1.y);
        }
        ulonglong2 q2 = wp[2], q3 = wp[3];
        #pragma unroll
        for (int k = 0; k < PTS; k++) {
            float hv = fmaxf(fmaf(px[k], w.x, fmaf(py[k], w.y, fmaf(pz[k], w.z, w.w))), 0.0f);
            unsigned long long h2 = packrep(hv);
            fma2(seg[k][4], h2, q2.x);
            fma2(seg[k][5], h2, q2.y);
            fma2(seg[k][6], h2, q3.x);
            fma2(seg[k][7], h2, q3.y);
        }
    }

    // resolve argmax + gumbel-selection per point (frees gumbel + seg registers)
    int sel[PTS];
    float argm[PTS];
    #pragma unroll
    for (int k = 0; k < PTS; k++) {
        float s[16];
        #pragma unroll
        for (int q = 0; q < 8; q++)
            unpack2(seg[k][q], s[2 * q], s[2 * q + 1]);

        int ia = 0; float m = s[0];
        #pragma unroll
        for (int p = 1; p < PP; p++)
            if (s[p] > m) { m = s[p]; ia = p; }
        argm[k] = (float)ia;

        int sl = 0; float vm = -1e30f;
        const float* gg = &g[k][0].x;
        #pragma unroll
        for (int p = 0; p < PP; p++) {
            float a = s[p] + gg[p];
            if (a > vm) { vm = a; sl = p; }
        }
        sel[k] = sl;
    }
    // coalesced argmax store (4 consecutive floats)
    *reinterpret_cast<float4*>(out + OFF_ARG + n0) =
        make_float4(argm[0], argm[1], argm[2], argm[3]);

    // epilogue: pc_out[t, n0..n0+3, :] = R[t,sel] @ x + t[t,sel]; 48B contiguous per t
    #pragma unroll 2
    for (int t = 0; t < TT; t++) {
        float o[PTS][3];
        #pragma unroll
        for (int k = 0; k < PTS; k++) {
            const float4* R = reinterpret_cast<const float4*>(s_R[t * PP + sel[k]]);
            float4 r0 = R[0], r1 = R[1], r2 = R[2];
            o[k][0] = fmaf(px[k], r0.x, fmaf(py[k], r0.y, fmaf(pz[k], r0.z, r2.y)));
            o[k][1] = fmaf(px[k], r0.w, fmaf(py[k], r1.x, fmaf(pz[k], r1.y, r2.z)));
            o[k][2] = fmaf(px[k], r1.z, fmaf(py[k], r1.w, fmaf(pz[k], r2.x, r2.w)));
        }
        float4* dst = reinterpret_cast<float4*>(out + (size_t)(t * NN + n0) * 3);
        dst[0] = make_float4(o[0][0], o[0][1], o[0][2], o[1][0]);
        dst[1] = make_float4(o[1][1], o[1][2], o[2][0], o[2][1]);
        dst[2] = make_float4(o[2][2], o[3][0], o[3][1], o[3][2]);
    }
}

extern "C" void kernel_launch(void* const* d_in, const int* in_sizes, int n_in,
                              void* d_out, int out_size) {
    (void)in_sizes; (void)n_in; (void)out_size;
    fused_kernel<<<NBLOCKS, NTHREADS>>>(
        (const float*)d_in[0],  // cano_pc
        (const float*)d_in[1],  // w1
        (const float*)d_in[2],  // b1
        (const float*)d_in[3],  // w2
        (const float*)d_in[4],  // b2
        (const float*)d_in[5],  // proposal_6d
        (const float*)d_in[6],  // proposal_t
        (const float*)d_in[7],  // gumbel
        (float*)d_out);
}